// round 16
// baseline (speedup 1.0000x reference)
#include <cuda_runtime.h>
#include <cuda_bf16.h>
#include <math.h>

#define BS   16384
#define NQ   16
#define HID  512

// ---------------- scratch ----------------
__device__ float g_s1[BS * HID];
__device__ float g_h1[BS * HID];
__device__ float g_d2[BS * HID];
__device__ float g_u2[BS * HID];
__device__ float g_g1[BS * HID];
__device__ float g_p [BS * HID];
__device__ float g_w [BS * HID];
__device__ float g_Q [(size_t)BS * 16 * HID];
__device__ float g_A [BS * NQ * NQ];
__device__ float g_rhs[BS * NQ];

// ---------------- f32x2 helpers ----------------
__device__ __forceinline__ void fma2(unsigned long long& d, unsigned long long a, unsigned long long b) {
    asm("fma.rn.f32x2 %0, %1, %2, %0;" : "+l"(d) : "l"(a), "l"(b));
}
__device__ __forceinline__ unsigned long long mul2(unsigned long long a, unsigned long long b) {
    unsigned long long d;
    asm("mul.rn.f32x2 %0, %1, %2;" : "=l"(d) : "l"(a), "l"(b));
    return d;
}
__device__ __forceinline__ unsigned long long pack2(float v) {
    unsigned long long r;
    asm("mov.b64 %0, {%1, %1};" : "=l"(r) : "f"(v));
    return r;
}
__device__ __forceinline__ unsigned long long pack2f(float lo, float hi) {
    unsigned long long r;
    asm("mov.b64 %0, {%1, %2};" : "=l"(r) : "f"(lo), "f"(hi));
    return r;
}
__device__ __forceinline__ float2 unpack2(unsigned long long v) {
    float2 r;
    asm("mov.b64 {%0, %1}, %2;" : "=f"(r.x), "=f"(r.y) : "l"(v));
    return r;
}

// ---------------- K1 ----------------
#define K1_SMEM ((32*512 + 256) * 4)
__global__ __launch_bounds__(256) void k1_layer1(const float* __restrict__ x,
                                                 const float* __restrict__ W1,
                                                 const float* __restrict__ b1) {
    extern __shared__ __align__(16) float sm1[];
    float* W1s = sm1;
    float* xs  = sm1 + 32 * 512;
    int tid = threadIdx.x;
    int b0  = blockIdx.x * 8;

    for (int it = 0; it < 16; ++it) {
        int idx = it * 256 + tid;
        reinterpret_cast<float4*>(W1s)[idx] = reinterpret_cast<const float4*>(W1)[idx];
    }
    xs[tid] = x[b0 * 32 + tid];
    __syncthreads();

    for (int q = 0; q < 8; ++q) {
        int idx = q * 256 + tid;
        int b  = idx >> 8;
        int k2 = (idx & 255) * 2;
        float2 bb = *reinterpret_cast<const float2*>(&b1[k2]);
        unsigned long long acc  = pack2f(bb.x, bb.y);
        unsigned long long accp = 0ull;
        const float* xr = xs + b * 32;
#pragma unroll
        for (int j = 0; j < 32; ++j) {
            float2 wv = *reinterpret_cast<const float2*>(&W1s[j * 512 + k2]);
            unsigned long long w2 = pack2f(wv.x, wv.y);
            fma2(acc, w2, pack2(xr[j]));
            if (j < 16) fma2(accp, w2, pack2(xr[16 + j]));
        }
        float2 a  = unpack2(acc);
        float2 ap = unpack2(accp);
        float sx = 1.f / (1.f + expf(-a.x));
        float sy = 1.f / (1.f + expf(-a.y));
        float hx = fmaxf(a.x, 0.f) + log1pf(expf(-fabsf(a.x)));
        float hy = fmaxf(a.y, 0.f) + log1pf(expf(-fabsf(a.y)));
        int gi = (b0 + b) * 512 + k2;
        float2 sv; sv.x = sx; sv.y = sy;
        float2 hv; hv.x = hx; hv.y = hy;
        *reinterpret_cast<float2*>(&g_s1[gi]) = sv;
        *reinterpret_cast<float2*>(&g_h1[gi]) = hv;
        *reinterpret_cast<float2*>(&g_p [gi]) = ap;
    }
}

// ---------------- bodies (round-15 verbatim, smem carved from pointer) ----------------

__device__ __forceinline__ void k4a_body(float* sm, const float* __restrict__ W1,
                                         const float* __restrict__ W2, int bx, int by) {
    float* W1s = sm;                  // [k*20 + i]
    float* s1s = W1s + 512 * 20;      // [k*9 + s]
    float* Bsb = s1s + 512 * 9;       // 2 x 2112

    int tid = threadIdx.x;
    int r0 = bx * 128;
    int n0 = by * 128;
    int s0 = bx * 8;
    int tx = (tid & 7) | ((tid >> 7) << 3);
    int ty = (tid >> 3) & 15;
    int sA = ty >> 1;
    int i0 = (ty & 1) * 8;

    int fkk = tid >> 5, fc4a = (tid & 31) * 4;
    int fkk1 = 8 + fkk;

    for (int idx = tid; idx < 16 * 512; idx += 256) {
        int i = idx >> 9, k = idx & 511;
        W1s[k * 20 + i] = W1[(16 + i) * 512 + k];
    }
    for (int idx = tid; idx < 8 * 512; idx += 256) {
        int s = idx >> 9, k = idx & 511;
        s1s[k * 9 + s] = g_s1[(size_t)(s0 + s) * 512 + k];
    }
    __syncthreads();

    {
        *reinterpret_cast<float4*>(&Bsb[fkk * 132 + fc4a]) =
            *reinterpret_cast<const float4*>(&W2[(size_t)fkk * 512 + n0 + fc4a]);
        *reinterpret_cast<float4*>(&Bsb[fkk1 * 132 + fc4a]) =
            *reinterpret_cast<const float4*>(&W2[(size_t)fkk1 * 512 + n0 + fc4a]);
    }
    __syncthreads();

    unsigned long long acc[8][4] = {};

    for (int kt = 0; kt < 32; ++kt) {
        const float* Bs = Bsb + (kt & 1) * 2112;
        float* Bsn = Bsb + ((kt + 1) & 1) * 2112;

        float4 bpre0, bpre1;
        if (kt < 31) {
            int k0n = (kt + 1) * 16;
            bpre0 = *reinterpret_cast<const float4*>(&W2[(size_t)(k0n + fkk) * 512 + n0 + fc4a]);
            bpre1 = *reinterpret_cast<const float4*>(&W2[(size_t)(k0n + fkk1) * 512 + n0 + fc4a]);
        }

        int k0 = kt * 16;
#pragma unroll
        for (int kk = 0; kk < 16; ++kk) {
            int k = k0 + kk;
            unsigned long long sv2 = pack2(s1s[k * 9 + sA]);
            ulonglong2 wa = *reinterpret_cast<const ulonglong2*>(&W1s[k * 20 + i0]);
            ulonglong2 wb = *reinterpret_cast<const ulonglong2*>(&W1s[k * 20 + i0 + 4]);
            ulonglong2 b01 = *reinterpret_cast<const ulonglong2*>(&Bs[kk * 132 + 4 * tx]);
            ulonglong2 b23 = *reinterpret_cast<const ulonglong2*>(&Bs[kk * 132 + 64 + 4 * tx]);
            unsigned long long p01 = mul2(wa.x, sv2);
            unsigned long long p23 = mul2(wa.y, sv2);
            unsigned long long p45 = mul2(wb.x, sv2);
            unsigned long long p67 = mul2(wb.y, sv2);
            float2 f;
            unsigned long long ap;
            f = unpack2(p01);
            ap = pack2(f.x);
            fma2(acc[0][0], b01.x, ap); fma2(acc[0][1], b01.y, ap);
            fma2(acc[0][2], b23.x, ap); fma2(acc[0][3], b23.y, ap);
            ap = pack2(f.y);
            fma2(acc[1][0], b01.x, ap); fma2(acc[1][1], b01.y, ap);
            fma2(acc[1][2], b23.x, ap); fma2(acc[1][3], b23.y, ap);
            f = unpack2(p23);
            ap = pack2(f.x);
            fma2(acc[2][0], b01.x, ap); fma2(acc[2][1], b01.y, ap);
            fma2(acc[2][2], b23.x, ap); fma2(acc[2][3], b23.y, ap);
            ap = pack2(f.y);
            fma2(acc[3][0], b01.x, ap); fma2(acc[3][1], b01.y, ap);
            fma2(acc[3][2], b23.x, ap); fma2(acc[3][3], b23.y, ap);
            f = unpack2(p45);
            ap = pack2(f.x);
            fma2(acc[4][0], b01.x, ap); fma2(acc[4][1], b01.y, ap);
            fma2(acc[4][2], b23.x, ap); fma2(acc[4][3], b23.y, ap);
            ap = pack2(f.y);
            fma2(acc[5][0], b01.x, ap); fma2(acc[5][1], b01.y, ap);
            fma2(acc[5][2], b23.x, ap); fma2(acc[5][3], b23.y, ap);
            f = unpack2(p67);
            ap = pack2(f.x);
            fma2(acc[6][0], b01.x, ap); fma2(acc[6][1], b01.y, ap);
            fma2(acc[6][2], b23.x, ap); fma2(acc[6][3], b23.y, ap);
            ap = pack2(f.y);
            fma2(acc[7][0], b01.x, ap); fma2(acc[7][1], b01.y, ap);
            fma2(acc[7][2], b23.x, ap); fma2(acc[7][3], b23.y, ap);
        }

        if (kt < 31) {
            *reinterpret_cast<float4*>(&Bsn[fkk * 132 + fc4a])  = bpre0;
            *reinterpret_cast<float4*>(&Bsn[fkk1 * 132 + fc4a]) = bpre1;
        }
        __syncthreads();
    }

#pragma unroll
    for (int rr = 0; rr < 8; ++rr) {
        size_t row = (size_t)r0 + ty * 8 + rr;
        float* qp = g_Q + row * 512 + n0 + 4 * tx;
        float2 f0 = unpack2(acc[rr][0]);
        float2 f1 = unpack2(acc[rr][1]);
        float2 f2 = unpack2(acc[rr][2]);
        float2 f3 = unpack2(acc[rr][3]);
        float4 v0; v0.x = f0.x; v0.y = f0.y; v0.z = f1.x; v0.w = f1.y;
        float4 v1; v1.x = f2.x; v1.y = f2.y; v1.z = f3.x; v1.w = f3.y;
        *reinterpret_cast<float4*>(qp)      = v0;
        *reinterpret_cast<float4*>(qp + 64) = v1;
    }
}

__device__ __forceinline__ void k2_body(float* sm, const float* __restrict__ W2,
                                        const float* __restrict__ b2,
                                        const float* __restrict__ W3, int bx, int by) {
    float* As  = sm;              // [16][68]
    float* As2 = sm + 16 * 68;    // [16][68]
    float* Bs  = As2 + 16 * 68;   // [16][132]
    int tid = threadIdx.x;
    int b0 = bx * 64;
    int m0 = by * 128;
    int ty = tid >> 4, tx = tid & 15;
    unsigned long long accv [4][4] = {};
    unsigned long long accv2[4][4] = {};

    int frow = tid >> 2, fc4 = tid & 3;

    for (int k0 = 0; k0 < HID; k0 += 16) {
        __syncthreads();
        {
            float4 hv = *reinterpret_cast<const float4*>(&g_h1[(b0 + frow) * HID + k0 + fc4 * 4]);
            float4 sv = *reinterpret_cast<const float4*>(&g_s1[(b0 + frow) * HID + k0 + fc4 * 4]);
            float4 pv = *reinterpret_cast<const float4*>(&g_p [(b0 + frow) * HID + k0 + fc4 * 4]);
            As[(fc4 * 4 + 0) * 68 + frow] = hv.x;
            As[(fc4 * 4 + 1) * 68 + frow] = hv.y;
            As[(fc4 * 4 + 2) * 68 + frow] = hv.z;
            As[(fc4 * 4 + 3) * 68 + frow] = hv.w;
            As2[(fc4 * 4 + 0) * 68 + frow] = sv.x * pv.x;
            As2[(fc4 * 4 + 1) * 68 + frow] = sv.y * pv.y;
            As2[(fc4 * 4 + 2) * 68 + frow] = sv.z * pv.z;
            As2[(fc4 * 4 + 3) * 68 + frow] = sv.w * pv.w;
#pragma unroll
            for (int it = 0; it < 2; ++it) {
                int idx = it * 256 + tid;
                int brow = idx >> 5, bc4 = idx & 31;
                *reinterpret_cast<float4*>(&Bs[brow * 132 + bc4 * 4]) =
                    *reinterpret_cast<const float4*>(&W2[(size_t)(k0 + brow) * HID + m0 + bc4 * 4]);
            }
        }
        __syncthreads();
#pragma unroll
        for (int kk = 0; kk < 16; ++kk) {
            ulonglong2 bv0 = *reinterpret_cast<const ulonglong2*>(&Bs[kk * 132 + 4 * tx]);
            ulonglong2 bv1 = *reinterpret_cast<const ulonglong2*>(&Bs[kk * 132 + 64 + 4 * tx]);
            float4 av  = *reinterpret_cast<const float4*>(&As [kk * 68 + ty * 4]);
            float4 av2 = *reinterpret_cast<const float4*>(&As2[kk * 68 + ty * 4]);
            const float* ap4  = &av.x;
            const float* ap42 = &av2.x;
#pragma unroll
            for (int i = 0; i < 4; ++i) {
                unsigned long long a = pack2(ap4[i]);
                fma2(accv[i][0], bv0.x, a);
                fma2(accv[i][1], bv0.y, a);
                fma2(accv[i][2], bv1.x, a);
                fma2(accv[i][3], bv1.y, a);
                unsigned long long a2 = pack2(ap42[i]);
                fma2(accv2[i][0], bv0.x, a2);
                fma2(accv2[i][1], bv0.y, a2);
                fma2(accv2[i][2], bv1.x, a2);
                fma2(accv2[i][3], bv1.y, a2);
            }
        }
    }
#pragma unroll
    for (int i = 0; i < 4; ++i) {
        int b = b0 + ty * 4 + i;
#pragma unroll
        for (int g = 0; g < 2; ++g) {
            int mbase = m0 + g * 64 + 4 * tx;
            float accr[4], accr2[4];
            float2 f;
            f = unpack2(accv[i][2 * g + 0]);  accr[0] = f.x;  accr[1] = f.y;
            f = unpack2(accv[i][2 * g + 1]);  accr[2] = f.x;  accr[3] = f.y;
            f = unpack2(accv2[i][2 * g + 0]); accr2[0] = f.x; accr2[1] = f.y;
            f = unpack2(accv2[i][2 * g + 1]); accr2[2] = f.x; accr2[3] = f.y;
            float4 b2v = *reinterpret_cast<const float4*>(&b2[mbase]);
            float4 w3v = *reinterpret_cast<const float4*>(&W3[mbase]);
            float bz[4] = {b2v.x, b2v.y, b2v.z, b2v.w};
            float wz[4] = {w3v.x, w3v.y, w3v.z, w3v.w};
            float4 d2o, u2o, wo;
            float* d2p = &d2o.x; float* u2p = &u2o.x; float* wp = &wo.x;
#pragma unroll
            for (int j = 0; j < 4; ++j) {
                float z = accr[j] + bz[j];
                float s = 1.f / (1.f + expf(-z));
                float d2v = s * (1.f - s) * wz[j];
                d2p[j] = d2v;
                u2p[j] = s * wz[j];
                wp[j]  = accr2[j] * d2v;
            }
            *reinterpret_cast<float4*>(&g_d2[b * HID + mbase]) = d2o;
            *reinterpret_cast<float4*>(&g_u2[b * HID + mbase]) = u2o;
            *reinterpret_cast<float4*>(&g_w [b * HID + mbase]) = wo;
        }
    }
}

__device__ __forceinline__ void k3_body(float* sm, const float* __restrict__ W2, int bx, int by) {
    float* As = sm;              // [16][68]
    float* Bs = sm + 16 * 68;    // [16][132]
    int tid = threadIdx.x;
    int b0  = bx * 64;
    int k00 = by * 128;
    int ty = tid >> 4, tx = tid & 15;
    unsigned long long accv[4][4] = {};

    int frow = tid >> 2, fc4 = tid & 3;

    for (int m0 = 0; m0 < HID; m0 += 16) {
        __syncthreads();
        {
            float4 uv = *reinterpret_cast<const float4*>(&g_u2[(b0 + frow) * HID + m0 + fc4 * 4]);
            As[(fc4 * 4 + 0) * 68 + frow] = uv.x;
            As[(fc4 * 4 + 1) * 68 + frow] = uv.y;
            As[(fc4 * 4 + 2) * 68 + frow] = uv.z;
            As[(fc4 * 4 + 3) * 68 + frow] = uv.w;
#pragma unroll
            for (int it = 0; it < 2; ++it) {
                int idx = it * 256 + tid;
                int bj = idx >> 2, bq4 = idx & 3;
                float4 wv = *reinterpret_cast<const float4*>(&W2[(size_t)(k00 + bj) * HID + m0 + bq4 * 4]);
                Bs[(bq4 * 4 + 0) * 132 + bj] = wv.x;
                Bs[(bq4 * 4 + 1) * 132 + bj] = wv.y;
                Bs[(bq4 * 4 + 2) * 132 + bj] = wv.z;
                Bs[(bq4 * 4 + 3) * 132 + bj] = wv.w;
            }
        }
        __syncthreads();
#pragma unroll
        for (int mm = 0; mm < 16; ++mm) {
            ulonglong2 bv0 = *reinterpret_cast<const ulonglong2*>(&Bs[mm * 132 + 4 * tx]);
            ulonglong2 bv1 = *reinterpret_cast<const ulonglong2*>(&Bs[mm * 132 + 64 + 4 * tx]);
            float4 av = *reinterpret_cast<const float4*>(&As[mm * 68 + ty * 4]);
            const float* ap4 = &av.x;
#pragma unroll
            for (int i = 0; i < 4; ++i) {
                unsigned long long a = pack2(ap4[i]);
                fma2(accv[i][0], bv0.x, a);
                fma2(accv[i][1], bv0.y, a);
                fma2(accv[i][2], bv1.x, a);
                fma2(accv[i][3], bv1.y, a);
            }
        }
    }
#pragma unroll
    for (int i = 0; i < 4; ++i) {
        int b = b0 + ty * 4 + i;
#pragma unroll
        for (int g = 0; g < 2; ++g) {
            int kbase = k00 + g * 64 + 4 * tx;
            float accr[4];
            float2 f;
            f = unpack2(accv[i][2 * g + 0]); accr[0] = f.x; accr[1] = f.y;
            f = unpack2(accv[i][2 * g + 1]); accr[2] = f.x; accr[3] = f.y;
            int gi = b * HID + kbase;
            float4 s4 = *reinterpret_cast<const float4*>(&g_s1[gi]);
            float ss[4] = {s4.x, s4.y, s4.z, s4.w};
            float4 u1o, d1o;
            float* u1p = &u1o.x; float* d1p = &d1o.x;
#pragma unroll
            for (int j = 0; j < 4; ++j) {
                float gv = accr[j];
                float s = ss[j];
                u1p[j] = s * gv;
                d1p[j] = s * (1.f - s) * gv;
            }
            *reinterpret_cast<float4*>(&g_h1[gi]) = u1o;
            *reinterpret_cast<float4*>(&g_g1[gi]) = d1o;
        }
    }
}

__device__ __forceinline__ void kjac_body(float* W1s, const float* __restrict__ W1, int bid) {
    int tid = threadIdx.x;
    int b0  = bid * 8;
    for (int idx = tid; idx < 32 * 512; idx += 256)
        W1s[(idx >> 9) * 516 + (idx & 511)] = W1[idx];
    __syncthreads();

    int s = tid >> 5, lane = tid & 31;
    int i = lane & 15, half = lane >> 4;
    int b = b0 + s;
    const float4* u4 = (const float4*)(g_h1 + (size_t)b * 512 + half * 256);
    const float4* d4 = (const float4*)(g_g1 + (size_t)b * 512 + half * 256);
    const float4* p4 = (const float4*)(g_p  + (size_t)b * 512 + half * 256);
    const float4* wJ = (const float4*)(W1s + i * 516 + half * 256);
    const float4* wR = (const float4*)(W1s + (16 + i) * 516 + half * 256);
    float accJ = 0.f, accR = 0.f;
#pragma unroll 4
    for (int t = 0; t < 64; ++t) {
        float4 u = u4[t], d = d4[t], p = p4[t];
        float4 wj = wJ[t], wr = wR[t];
        accJ = fmaf(wj.x, u.x, accJ);
        accJ = fmaf(wj.y, u.y, accJ);
        accJ = fmaf(wj.z, u.z, accJ);
        accJ = fmaf(wj.w, u.w, accJ);
        accR = fmaf(wr.x, d.x * p.x, accR);
        accR = fmaf(wr.y, d.y * p.y, accR);
        accR = fmaf(wr.z, d.z * p.z, accR);
        accR = fmaf(wr.w, d.w * p.w, accR);
    }
    accJ += __shfl_xor_sync(0xffffffffu, accJ, 16);
    accR += __shfl_xor_sync(0xffffffffu, accR, 16);
    if (lane < 16) g_rhs[(size_t)b * 16 + i] = accJ - accR;
}

// ---------------- fat kernels: K4a chunk + rider ----------------
#define K4A_FLOATS (512*20 + 512*9 + 2*16*132)
#define FAT_SMEM   (K4A_FLOATS * 4)
#define C1 768
#define C2 768
#define C3 512

__global__ __launch_bounds__(256, 2) void fat1(const float* __restrict__ W1,
                                               const float* __restrict__ W2,
                                               const float* __restrict__ b2,
                                               const float* __restrict__ W3) {
    extern __shared__ __align__(16) float sm[];
    if (blockIdx.x < C1) k4a_body(sm, W1, W2, blockIdx.x, blockIdx.y);
    else                 k2_body(sm, W2, b2, W3, blockIdx.x - C1, blockIdx.y);
}

__global__ __launch_bounds__(256, 2) void fat2(const float* __restrict__ W1,
                                               const float* __restrict__ W2) {
    extern __shared__ __align__(16) float sm[];
    if (blockIdx.x < C2) k4a_body(sm, W1, W2, C1 + blockIdx.x, blockIdx.y);
    else                 k3_body(sm, W2, blockIdx.x - C2, blockIdx.y);
}

__global__ __launch_bounds__(256, 2) void fat3(const float* __restrict__ W1,
                                               const float* __restrict__ W2) {
    extern __shared__ __align__(16) float sm[];
    if (blockIdx.x < C3) k4a_body(sm, W1, W2, C1 + C2 + blockIdx.x, blockIdx.y);
    else                 kjac_body(sm, W1, (blockIdx.x - C3) + blockIdx.y * 512);
}

// ---------------- K4b (round-15) ----------------
#define K4B_FLOATS (16*520 + 128*68 + 8*512 + 8*64 + 8*64)
#define K4B_SMEM   (K4B_FLOATS * 4)

__global__ __launch_bounds__(256, 2) void k4b_assemble(const float* __restrict__ W1) {
    extern __shared__ __align__(16) float smb[];
    float* W1t = smb;
    float* Qc  = W1t + 16 * 520;
    float* d1s = Qc + 128 * 68;
    float* d2c = d1s + 8 * 512;
    float* wc  = d2c + 8 * 64;

    int tid = threadIdx.x;
    int b0  = blockIdx.x * 8;

    for (int idx = tid; idx < 16 * 512; idx += 256) {
        int i = idx >> 9, k = idx & 511;
        W1t[i * 520 + k] = W1[(16 + i) * 512 + k];
    }
    for (int idx = tid; idx < 8 * 512; idx += 256)
        d1s[idx] = g_g1[(size_t)b0 * 512 + idx];

    int s = tid >> 5, lane = tid & 31;
    int rg = lane >> 3, cg = lane & 7;

    unsigned long long A01[4] = {};
    float rhs2[4] = {};

    for (int mc = 0; mc < 8; ++mc) {
        int m0 = mc * 64;
        __syncthreads();
#pragma unroll
        for (int it = 0; it < 8; ++it) {
            int idx = it * 256 + tid;
            int ss = idx >> 8, rem = idx & 255;
            int i = rem >> 4, c4 = rem & 15;
            *reinterpret_cast<float4*>(&Qc[(ss * 16 + i) * 68 + c4 * 4]) =
                *reinterpret_cast<const float4*>(&g_Q[((size_t)(b0 + ss) * 16 + i) * 512 + m0 + c4 * 4]);
        }
        for (int idx = tid; idx < 512; idx += 256) {
            int ss = idx >> 6, m = idx & 63;
            d2c[idx] = g_d2[(size_t)(b0 + ss) * 512 + m0 + m];
            wc[idx]  = g_w [(size_t)(b0 + ss) * 512 + m0 + m];
        }
        __syncthreads();

        const float* qb = Qc + s * 16 * 68;
        const float* dp = d2c + s * 64;
        const float* wp = wc + s * 64;
#pragma unroll 2
        for (int m4 = 0; m4 < 16; ++m4) {
            float d2v[4], wv[4], qj0[4], qj1[4];
            *reinterpret_cast<float4*>(d2v) = *reinterpret_cast<const float4*>(dp + m4 * 4);
            *reinterpret_cast<float4*>(wv)  = *reinterpret_cast<const float4*>(wp + m4 * 4);
            *reinterpret_cast<float4*>(qj0) = *reinterpret_cast<const float4*>(qb + (2 * cg) * 68 + m4 * 4);
            *reinterpret_cast<float4*>(qj1) = *reinterpret_cast<const float4*>(qb + (2 * cg + 1) * 68 + m4 * 4);
            float qi[4][4];
#pragma unroll
            for (int rr = 0; rr < 4; ++rr)
                *reinterpret_cast<float4*>(qi[rr]) =
                    *reinterpret_cast<const float4*>(qb + (4 * rg + rr) * 68 + m4 * 4);
#pragma unroll
            for (int e = 0; e < 4; ++e) {
                unsigned long long qj = pack2f(qj0[e], qj1[e]);
#pragma unroll
                for (int rr = 0; rr < 4; ++rr) {
                    float t = qi[rr][e] * d2v[e];
                    fma2(A01[rr], qj, pack2(t));
                    rhs2[rr] = fmaf(qi[rr][e], wv[e], rhs2[rr]);
                }
            }
        }
    }

    {
        const float* d1p = d1s + s * 512;
#pragma unroll 2
        for (int k4 = 0; k4 < 128; ++k4) {
            float d1v[4], wj0[4], wj1[4];
            *reinterpret_cast<float4*>(d1v) = *reinterpret_cast<const float4*>(d1p + k4 * 4);
            *reinterpret_cast<float4*>(wj0) = *reinterpret_cast<const float4*>(W1t + (2 * cg) * 520 + k4 * 4);
            *reinterpret_cast<float4*>(wj1) = *reinterpret_cast<const float4*>(W1t + (2 * cg + 1) * 520 + k4 * 4);
            float wi[4][4];
#pragma unroll
            for (int rr = 0; rr < 4; ++rr)
                *reinterpret_cast<float4*>(wi[rr]) =
                    *reinterpret_cast<const float4*>(W1t + (4 * rg + rr) * 520 + k4 * 4);
#pragma unroll
            for (int e = 0; e < 4; ++e) {
                unsigned long long wj = pack2f(wj0[e], wj1[e]);
#pragma unroll
                for (int rr = 0; rr < 4; ++rr) {
                    float t = wi[rr][e] * d1v[e];
                    fma2(A01[rr], wj, pack2(t));
                }
            }
        }
    }

    int b = b0 + s;
#pragma unroll
    for (int rr = 0; rr < 4; ++rr) {
        int i = 4 * rg + rr;
        float* Ar = g_A + ((size_t)b * 16 + i) * 16;
        float2 f = unpack2(A01[rr]);
        Ar[2 * cg]     = f.x;
        Ar[2 * cg + 1] = f.y;
        if (cg == 0) {
            size_t ob = (size_t)b * 16 + i;
            g_rhs[ob] -= rhs2[rr];
        }
    }
}

// ---------------- K5 (round-15) ----------------
#define PINV_RCOND 1.9073486e-5f
#define JACOBI_SWEEPS 6

__global__ __launch_bounds__(256) void k5_pinv(const float* __restrict__ x,
                                               float* __restrict__ out) {
    __shared__ float sm[16 * 592];
    int tid = threadIdx.x;
    int sI = tid >> 4;
    int r  = tid & 15;
    int b  = blockIdx.x * 16 + sI;

    float* As = sm + sI * 592;
    float* Vs = As + 272;
    float* ys = Vs + 272;
    float* rs = ys + 16;

    {
        const float* Ag = g_A + ((size_t)b * 16 + r) * 16;
#pragma unroll
        for (int j = 0; j < 16; ++j) {
            As[r * 17 + j] = Ag[j];
            Vs[r * 17 + j] = (r == j) ? 1.f : 0.f;
        }
        rs[r] = g_rhs[(size_t)b * 16 + r];
    }
    __syncwarp();

    for (int sweep = 0; sweep < JACOBI_SWEEPS; ++sweep) {
        for (int p = 0; p < 15; ++p) {
            for (int q = p + 1; q < 16; ++q) {
                float apq = As[p * 17 + q];
                float app = As[p * 17 + p];
                float aqq = As[q * 17 + q];
                float aip = As[r * 17 + p];
                float aiq = As[r * 17 + q];
                float vip = Vs[r * 17 + p];
                float viq = Vs[r * 17 + q];
                __syncwarp();
                float tau = (aqq - app) / (2.f * apq);
                float tt  = copysignf(1.f, tau) / (fabsf(tau) + sqrtf(fmaf(tau, tau, 1.f)));
                float t   = (fabsf(apq) > 0.f) ? tt : 0.f;
                float c   = 1.f / sqrtf(fmaf(t, t, 1.f));
                float s   = t * c;
                float nip = c * aip - s * aiq;
                float niq = s * aip + c * aiq;
                if (r != p && r != q) {
                    As[r * 17 + p] = nip; As[p * 17 + r] = nip;
                    As[r * 17 + q] = niq; As[q * 17 + r] = niq;
                }
                if (r == p) {
                    As[p * 17 + p] = app - t * apq;
                    As[q * 17 + q] = aqq + t * apq;
                    As[p * 17 + q] = 0.f;
                    As[q * 17 + p] = 0.f;
                }
                Vs[r * 17 + p] = c * vip - s * viq;
                Vs[r * 17 + q] = s * vip + c * viq;
                __syncwarp();
            }
        }
    }

    float lam = As[r * 17 + r];
    float m = fabsf(lam);
#pragma unroll
    for (int off = 8; off > 0; off >>= 1)
        m = fmaxf(m, __shfl_xor_sync(0xffffffffu, m, off));
    float cutoff = PINV_RCOND * m;

    float acc = 0.f;
#pragma unroll
    for (int j = 0; j < 16; ++j) acc = fmaf(Vs[j * 17 + r], rs[j], acc);
    ys[r] = (fabsf(lam) > cutoff) ? (acc / lam) : 0.f;
    __syncwarp();

    float qdd = 0.f;
#pragma unroll
    for (int j = 0; j < 16; ++j) qdd = fmaf(Vs[r * 17 + j], ys[j], qdd);

    out[(size_t)b * 32 + 16 + r] = qdd;
    out[(size_t)b * 32 + r]      = x[(size_t)b * 32 + 16 + r];
}

// ---------------- launch ----------------
extern "C" void kernel_launch(void* const* d_in, const int* in_sizes, int n_in,
                              void* d_out, int out_size) {
    const float* x  = (const float*)d_in[0];
    const float* W1 = (const float*)d_in[1];
    const float* b1 = (const float*)d_in[2];
    const float* W2 = (const float*)d_in[3];
    const float* b2 = (const float*)d_in[4];
    const float* W3 = (const float*)d_in[5];
    float* out = (float*)d_out;
    (void)in_sizes; (void)n_in; (void)out_size;

    cudaFuncSetAttribute(k1_layer1,    cudaFuncAttributeMaxDynamicSharedMemorySize, K1_SMEM);
    cudaFuncSetAttribute(fat1,         cudaFuncAttributeMaxDynamicSharedMemorySize, FAT_SMEM);
    cudaFuncSetAttribute(fat2,         cudaFuncAttributeMaxDynamicSharedMemorySize, FAT_SMEM);
    cudaFuncSetAttribute(fat3,         cudaFuncAttributeMaxDynamicSharedMemorySize, FAT_SMEM);
    cudaFuncSetAttribute(k4b_assemble, cudaFuncAttributeMaxDynamicSharedMemorySize, K4B_SMEM);

    k1_layer1<<<BS / 8, 256, K1_SMEM>>>(x, W1, b1);
    fat1<<<dim3(C1 + 256, 4), 256, FAT_SMEM>>>(W1, W2, b2, W3);   // K4a[0:768] ∪ K2
    fat2<<<dim3(C2 + 256, 4), 256, FAT_SMEM>>>(W1, W2);           // K4a[768:1536] ∪ K3
    fat3<<<dim3(C3 + 512, 4), 256, FAT_SMEM>>>(W1, W2);           // K4a[1536:2048] ∪ k_jac
    k4b_assemble<<<BS / 8, 256, K4B_SMEM>>>(W1);
    k5_pinv<<<BS / 16, 256>>>(x, out);
}

// round 17
// speedup vs baseline: 1.0227x; 1.0227x over previous
#include <cuda_runtime.h>
#include <cuda_bf16.h>
#include <math.h>

#define BS   16384
#define NQ   16
#define HID  512

// ---------------- scratch ----------------
__device__ float g_s1[BS * HID];
__device__ float g_h1[BS * HID];
__device__ float g_d2[BS * HID];
__device__ float g_u2[BS * HID];
__device__ float g_g1[BS * HID];
__device__ float g_p [BS * HID];
__device__ float g_w [BS * HID];
__device__ float g_Q [(size_t)BS * 16 * HID];
__device__ float g_A [BS * NQ * NQ];
__device__ float g_rhs[BS * NQ];

// ---------------- f32x2 helpers ----------------
__device__ __forceinline__ void fma2(unsigned long long& d, unsigned long long a, unsigned long long b) {
    asm("fma.rn.f32x2 %0, %1, %2, %0;" : "+l"(d) : "l"(a), "l"(b));
}
__device__ __forceinline__ unsigned long long pack2(float v) {
    unsigned long long r;
    asm("mov.b64 %0, {%1, %1};" : "=l"(r) : "f"(v));
    return r;
}
__device__ __forceinline__ unsigned long long pack2f(float lo, float hi) {
    unsigned long long r;
    asm("mov.b64 %0, {%1, %2};" : "=l"(r) : "f"(lo), "f"(hi));
    return r;
}
__device__ __forceinline__ float2 unpack2(unsigned long long v) {
    float2 r;
    asm("mov.b64 {%0, %1}, %2;" : "=f"(r.x), "=f"(r.y) : "l"(v));
    return r;
}

// ---------------- K1: z1 = x@W1 + b1 -> s1, h1 ; p = W1_top^T qd ----------------
#define K1_SMEM ((32*512 + 256) * 4)
__global__ __launch_bounds__(256) void k1_layer1(const float* __restrict__ x,
                                                 const float* __restrict__ W1,
                                                 const float* __restrict__ b1) {
    extern __shared__ __align__(16) float sm1[];
    float* W1s = sm1;
    float* xs  = sm1 + 32 * 512;
    int tid = threadIdx.x;
    int b0  = blockIdx.x * 8;

    for (int it = 0; it < 16; ++it) {
        int idx = it * 256 + tid;
        reinterpret_cast<float4*>(W1s)[idx] = reinterpret_cast<const float4*>(W1)[idx];
    }
    xs[tid] = x[b0 * 32 + tid];
    __syncthreads();

    for (int q = 0; q < 8; ++q) {
        int idx = q * 256 + tid;
        int b  = idx >> 8;
        int k2 = (idx & 255) * 2;
        float2 bb = *reinterpret_cast<const float2*>(&b1[k2]);
        unsigned long long acc  = pack2f(bb.x, bb.y);
        unsigned long long accp = 0ull;
        const float* xr = xs + b * 32;
#pragma unroll
        for (int j = 0; j < 32; ++j) {
            float2 wv = *reinterpret_cast<const float2*>(&W1s[j * 512 + k2]);
            unsigned long long w2 = pack2f(wv.x, wv.y);
            fma2(acc, w2, pack2(xr[j]));
            if (j < 16) fma2(accp, w2, pack2(xr[16 + j]));
        }
        float2 a  = unpack2(acc);
        float2 ap = unpack2(accp);
        float sx = 1.f / (1.f + expf(-a.x));
        float sy = 1.f / (1.f + expf(-a.y));
        float hx = fmaxf(a.x, 0.f) + log1pf(expf(-fabsf(a.x)));
        float hy = fmaxf(a.y, 0.f) + log1pf(expf(-fabsf(a.y)));
        int gi = (b0 + b) * 512 + k2;
        float2 sv; sv.x = sx; sv.y = sy;
        float2 hv; hv.x = hx; hv.y = hy;
        *reinterpret_cast<float2*>(&g_s1[gi]) = sv;
        *reinterpret_cast<float2*>(&g_h1[gi]) = hv;
        *reinterpret_cast<float2*>(&g_p [gi]) = ap;
    }
}

// ---------------- K2 (round-15) ----------------
__global__ __launch_bounds__(256) void k2_layer2(const float* __restrict__ W2,
                                                 const float* __restrict__ b2,
                                                 const float* __restrict__ W3) {
    __shared__ __align__(16) float As [16][68];
    __shared__ __align__(16) float As2[16][68];
    __shared__ __align__(16) float Bs [16][132];
    int tid = threadIdx.x;
    int b0 = blockIdx.x * 64;
    int m0 = blockIdx.y * 128;
    int ty = tid >> 4, tx = tid & 15;
    unsigned long long accv [4][4] = {};
    unsigned long long accv2[4][4] = {};

    int frow = tid >> 2, fc4 = tid & 3;

    for (int k0 = 0; k0 < HID; k0 += 16) {
        __syncthreads();
        {
            float4 hv = *reinterpret_cast<const float4*>(&g_h1[(b0 + frow) * HID + k0 + fc4 * 4]);
            float4 sv = *reinterpret_cast<const float4*>(&g_s1[(b0 + frow) * HID + k0 + fc4 * 4]);
            float4 pv = *reinterpret_cast<const float4*>(&g_p [(b0 + frow) * HID + k0 + fc4 * 4]);
            As[fc4 * 4 + 0][frow] = hv.x;
            As[fc4 * 4 + 1][frow] = hv.y;
            As[fc4 * 4 + 2][frow] = hv.z;
            As[fc4 * 4 + 3][frow] = hv.w;
            As2[fc4 * 4 + 0][frow] = sv.x * pv.x;
            As2[fc4 * 4 + 1][frow] = sv.y * pv.y;
            As2[fc4 * 4 + 2][frow] = sv.z * pv.z;
            As2[fc4 * 4 + 3][frow] = sv.w * pv.w;
#pragma unroll
            for (int it = 0; it < 2; ++it) {
                int idx = it * 256 + tid;
                int brow = idx >> 5, bc4 = idx & 31;
                *reinterpret_cast<float4*>(&Bs[brow][bc4 * 4]) =
                    *reinterpret_cast<const float4*>(&W2[(size_t)(k0 + brow) * HID + m0 + bc4 * 4]);
            }
        }
        __syncthreads();
#pragma unroll
        for (int kk = 0; kk < 16; ++kk) {
            ulonglong2 bv0 = *reinterpret_cast<const ulonglong2*>(&Bs[kk][4 * tx]);
            ulonglong2 bv1 = *reinterpret_cast<const ulonglong2*>(&Bs[kk][64 + 4 * tx]);
            float4 av  = *reinterpret_cast<const float4*>(&As [kk][ty * 4]);
            float4 av2 = *reinterpret_cast<const float4*>(&As2[kk][ty * 4]);
            const float* ap4  = &av.x;
            const float* ap42 = &av2.x;
#pragma unroll
            for (int i = 0; i < 4; ++i) {
                unsigned long long a = pack2(ap4[i]);
                fma2(accv[i][0], bv0.x, a);
                fma2(accv[i][1], bv0.y, a);
                fma2(accv[i][2], bv1.x, a);
                fma2(accv[i][3], bv1.y, a);
                unsigned long long a2 = pack2(ap42[i]);
                fma2(accv2[i][0], bv0.x, a2);
                fma2(accv2[i][1], bv0.y, a2);
                fma2(accv2[i][2], bv1.x, a2);
                fma2(accv2[i][3], bv1.y, a2);
            }
        }
    }
#pragma unroll
    for (int i = 0; i < 4; ++i) {
        int b = b0 + ty * 4 + i;
#pragma unroll
        for (int g = 0; g < 2; ++g) {
            int mbase = m0 + g * 64 + 4 * tx;
            float accr[4], accr2[4];
            float2 f;
            f = unpack2(accv[i][2 * g + 0]);  accr[0] = f.x;  accr[1] = f.y;
            f = unpack2(accv[i][2 * g + 1]);  accr[2] = f.x;  accr[3] = f.y;
            f = unpack2(accv2[i][2 * g + 0]); accr2[0] = f.x; accr2[1] = f.y;
            f = unpack2(accv2[i][2 * g + 1]); accr2[2] = f.x; accr2[3] = f.y;
            float4 b2v = *reinterpret_cast<const float4*>(&b2[mbase]);
            float4 w3v = *reinterpret_cast<const float4*>(&W3[mbase]);
            float bz[4] = {b2v.x, b2v.y, b2v.z, b2v.w};
            float wz[4] = {w3v.x, w3v.y, w3v.z, w3v.w};
            float4 d2o, u2o, wo;
            float* d2p = &d2o.x; float* u2p = &u2o.x; float* wp = &wo.x;
#pragma unroll
            for (int j = 0; j < 4; ++j) {
                float z = accr[j] + bz[j];
                float s = 1.f / (1.f + expf(-z));
                float d2v = s * (1.f - s) * wz[j];
                d2p[j] = d2v;
                u2p[j] = s * wz[j];
                wp[j]  = accr2[j] * d2v;
            }
            *reinterpret_cast<float4*>(&g_d2[b * HID + mbase]) = d2o;
            *reinterpret_cast<float4*>(&g_u2[b * HID + mbase]) = u2o;
            *reinterpret_cast<float4*>(&g_w [b * HID + mbase]) = wo;
        }
    }
}

// ---------------- K3 (round-15) ----------------
__global__ __launch_bounds__(256) void k3_g1(const float* __restrict__ W2) {
    __shared__ __align__(16) float As[16][68];
    __shared__ __align__(16) float Bs[16][132];
    int tid = threadIdx.x;
    int b0  = blockIdx.x * 64;
    int k00 = blockIdx.y * 128;
    int ty = tid >> 4, tx = tid & 15;
    unsigned long long accv[4][4] = {};

    int frow = tid >> 2, fc4 = tid & 3;

    for (int m0 = 0; m0 < HID; m0 += 16) {
        __syncthreads();
        {
            float4 uv = *reinterpret_cast<const float4*>(&g_u2[(b0 + frow) * HID + m0 + fc4 * 4]);
            As[fc4 * 4 + 0][frow] = uv.x;
            As[fc4 * 4 + 1][frow] = uv.y;
            As[fc4 * 4 + 2][frow] = uv.z;
            As[fc4 * 4 + 3][frow] = uv.w;
#pragma unroll
            for (int it = 0; it < 2; ++it) {
                int idx = it * 256 + tid;
                int bj = idx >> 2, bq4 = idx & 3;
                float4 wv = *reinterpret_cast<const float4*>(&W2[(size_t)(k00 + bj) * HID + m0 + bq4 * 4]);
                Bs[bq4 * 4 + 0][bj] = wv.x;
                Bs[bq4 * 4 + 1][bj] = wv.y;
                Bs[bq4 * 4 + 2][bj] = wv.z;
                Bs[bq4 * 4 + 3][bj] = wv.w;
            }
        }
        __syncthreads();
#pragma unroll
        for (int mm = 0; mm < 16; ++mm) {
            ulonglong2 bv0 = *reinterpret_cast<const ulonglong2*>(&Bs[mm][4 * tx]);
            ulonglong2 bv1 = *reinterpret_cast<const ulonglong2*>(&Bs[mm][64 + 4 * tx]);
            float4 av = *reinterpret_cast<const float4*>(&As[mm][ty * 4]);
            const float* ap4 = &av.x;
#pragma unroll
            for (int i = 0; i < 4; ++i) {
                unsigned long long a = pack2(ap4[i]);
                fma2(accv[i][0], bv0.x, a);
                fma2(accv[i][1], bv0.y, a);
                fma2(accv[i][2], bv1.x, a);
                fma2(accv[i][3], bv1.y, a);
            }
        }
    }
#pragma unroll
    for (int i = 0; i < 4; ++i) {
        int b = b0 + ty * 4 + i;
#pragma unroll
        for (int g = 0; g < 2; ++g) {
            int kbase = k00 + g * 64 + 4 * tx;
            float accr[4];
            float2 f;
            f = unpack2(accv[i][2 * g + 0]); accr[0] = f.x; accr[1] = f.y;
            f = unpack2(accv[i][2 * g + 1]); accr[2] = f.x; accr[3] = f.y;
            int gi = b * HID + kbase;
            float4 s4 = *reinterpret_cast<const float4*>(&g_s1[gi]);
            float ss[4] = {s4.x, s4.y, s4.z, s4.w};
            float4 u1o, d1o;
            float* u1p = &u1o.x; float* d1p = &d1o.x;
#pragma unroll
            for (int j = 0; j < 4; ++j) {
                float gv = accr[j];
                float s = ss[j];
                u1p[j] = s * gv;
                d1p[j] = s * (1.f - s) * gv;
            }
            *reinterpret_cast<float4*>(&g_h1[gi]) = u1o;
            *reinterpret_cast<float4*>(&g_g1[gi]) = d1o;
        }
    }
}

// ---------------- K_jac (round-15) ----------------
#define KJ_SMEM (32 * 516 * 4)
__global__ __launch_bounds__(256) void k_jac(const float* __restrict__ W1) {
    extern __shared__ __align__(16) float W1s[];
    int tid = threadIdx.x;
    int b0  = blockIdx.x * 8;
    for (int idx = tid; idx < 32 * 512; idx += 256)
        W1s[(idx >> 9) * 516 + (idx & 511)] = W1[idx];
    __syncthreads();

    int s = tid >> 5, lane = tid & 31;
    int i = lane & 15, half = lane >> 4;
    int b = b0 + s;
    const float4* u4 = (const float4*)(g_h1 + (size_t)b * 512 + half * 256);
    const float4* d4 = (const float4*)(g_g1 + (size_t)b * 512 + half * 256);
    const float4* p4 = (const float4*)(g_p  + (size_t)b * 512 + half * 256);
    const float4* wJ = (const float4*)(W1s + i * 516 + half * 256);
    const float4* wR = (const float4*)(W1s + (16 + i) * 516 + half * 256);
    float accJ = 0.f, accR = 0.f;
#pragma unroll 4
    for (int t = 0; t < 64; ++t) {
        float4 u = u4[t], d = d4[t], p = p4[t];
        float4 wj = wJ[t], wr = wR[t];
        accJ = fmaf(wj.x, u.x, accJ);
        accJ = fmaf(wj.y, u.y, accJ);
        accJ = fmaf(wj.z, u.z, accJ);
        accJ = fmaf(wj.w, u.w, accJ);
        accR = fmaf(wr.x, d.x * p.x, accR);
        accR = fmaf(wr.y, d.y * p.y, accR);
        accR = fmaf(wr.z, d.z * p.z, accR);
        accR = fmaf(wr.w, d.w * p.w, accR);
    }
    accJ += __shfl_xor_sync(0xffffffffu, accJ, 16);
    accR += __shfl_xor_sync(0xffffffffu, accR, 16);
    if (lane < 16) g_rhs[(size_t)b * 16 + i] = accJ - accR;
}

// ---------------- K4a: Q GEMM — staged A products, double-buffered (bit-exact) ----------------
// smem floats: W1s 512*20 | s1s 512*9 | Bsb 2*2112 | Apb 2*2112
#define K4A_FLOATS (512*20 + 512*9 + 2*2112 + 2*2112)
#define K4A_SMEM   (K4A_FLOATS * 4)

__global__ __launch_bounds__(256, 2) void k4a_qgemm(const float* __restrict__ W1,
                                                    const float* __restrict__ W2) {
    extern __shared__ __align__(16) float sma[];
    float* W1s = sma;                 // [k*20 + i]
    float* s1s = W1s + 512 * 20;      // [k*9 + s]
    float* Bsb = s1s + 512 * 9;       // 2 x [kk*132 + col]
    float* Apb = Bsb + 2 * 2112;      // 2 x [kk*132 + row]  (dense products)

    int tid = threadIdx.x;
    int r0 = blockIdx.x * 128;
    int n0 = blockIdx.y * 128;
    int s0 = blockIdx.x * 8;
    int tx = (tid & 7) | ((tid >> 7) << 3);
    int ty = (tid >> 3) & 15;

    int fkk = tid >> 5, fc4a = (tid & 31) * 4;
    int fkk1 = 8 + fkk;
    int akk = tid >> 4, arow = (tid & 15) * 8;   // A-fill: thread fills 8 consecutive rows of one kk... (2 kks via +16)

    for (int idx = tid; idx < 16 * 512; idx += 256) {
        int i = idx >> 9, k = idx & 511;
        W1s[k * 20 + i] = W1[(16 + i) * 512 + k];
    }
    for (int idx = tid; idx < 8 * 512; idx += 256) {
        int s = idx >> 9, k = idx & 511;
        s1s[k * 9 + s] = g_s1[(size_t)(s0 + s) * 512 + k];
    }
    __syncthreads();

    // prime buffer 0 (kt = 0): B rows 0..15 and A products k 0..15
    {
        *reinterpret_cast<float4*>(&Bsb[fkk * 132 + fc4a]) =
            *reinterpret_cast<const float4*>(&W2[(size_t)fkk * 512 + n0 + fc4a]);
        *reinterpret_cast<float4*>(&Bsb[fkk1 * 132 + fc4a]) =
            *reinterpret_cast<const float4*>(&W2[(size_t)fkk1 * 512 + n0 + fc4a]);
#pragma unroll
        for (int h = 0; h < 8; ++h) {
            int row = arow + h;
            Apb[akk * 132 + row] = W1s[akk * 20 + (row & 15)] * s1s[akk * 9 + (row >> 4)];
        }
    }
    __syncthreads();

    unsigned long long acc[8][4] = {};

    for (int kt = 0; kt < 32; ++kt) {
        const float* Bs = Bsb + (kt & 1) * 2112;
        const float* Ap = Apb + (kt & 1) * 2112;
        float* Bsn = Bsb + ((kt + 1) & 1) * 2112;
        float* Apn = Apb + ((kt + 1) & 1) * 2112;

        float4 bpre0, bpre1;
        if (kt < 31) {
            int k0n = (kt + 1) * 16;
            bpre0 = *reinterpret_cast<const float4*>(&W2[(size_t)(k0n + fkk) * 512 + n0 + fc4a]);
            bpre1 = *reinterpret_cast<const float4*>(&W2[(size_t)(k0n + fkk1) * 512 + n0 + fc4a]);
        }

#pragma unroll
        for (int kk = 0; kk < 16; ++kk) {
            float4 av0 = *reinterpret_cast<const float4*>(&Ap[kk * 132 + ty * 8]);
            float4 av1 = *reinterpret_cast<const float4*>(&Ap[kk * 132 + ty * 8 + 4]);
            ulonglong2 b01 = *reinterpret_cast<const ulonglong2*>(&Bs[kk * 132 + 4 * tx]);
            ulonglong2 b23 = *reinterpret_cast<const ulonglong2*>(&Bs[kk * 132 + 64 + 4 * tx]);
            unsigned long long ap;
            ap = pack2(av0.x);
            fma2(acc[0][0], b01.x, ap); fma2(acc[0][1], b01.y, ap);
            fma2(acc[0][2], b23.x, ap); fma2(acc[0][3], b23.y, ap);
            ap = pack2(av0.y);
            fma2(acc[1][0], b01.x, ap); fma2(acc[1][1], b01.y, ap);
            fma2(acc[1][2], b23.x, ap); fma2(acc[1][3], b23.y, ap);
            ap = pack2(av0.z);
            fma2(acc[2][0], b01.x, ap); fma2(acc[2][1], b01.y, ap);
            fma2(acc[2][2], b23.x, ap); fma2(acc[2][3], b23.y, ap);
            ap = pack2(av0.w);
            fma2(acc[3][0], b01.x, ap); fma2(acc[3][1], b01.y, ap);
            fma2(acc[3][2], b23.x, ap); fma2(acc[3][3], b23.y, ap);
            ap = pack2(av1.x);
            fma2(acc[4][0], b01.x, ap); fma2(acc[4][1], b01.y, ap);
            fma2(acc[4][2], b23.x, ap); fma2(acc[4][3], b23.y, ap);
            ap = pack2(av1.y);
            fma2(acc[5][0], b01.x, ap); fma2(acc[5][1], b01.y, ap);
            fma2(acc[5][2], b23.x, ap); fma2(acc[5][3], b23.y, ap);
            ap = pack2(av1.z);
            fma2(acc[6][0], b01.x, ap); fma2(acc[6][1], b01.y, ap);
            fma2(acc[6][2], b23.x, ap); fma2(acc[6][3], b23.y, ap);
            ap = pack2(av1.w);
            fma2(acc[7][0], b01.x, ap); fma2(acc[7][1], b01.y, ap);
            fma2(acc[7][2], b23.x, ap); fma2(acc[7][3], b23.y, ap);
        }

        if (kt < 31) {
            *reinterpret_cast<float4*>(&Bsn[fkk * 132 + fc4a])  = bpre0;
            *reinterpret_cast<float4*>(&Bsn[fkk1 * 132 + fc4a]) = bpre1;
            int k0n = (kt + 1) * 16;
#pragma unroll
            for (int h = 0; h < 8; ++h) {
                int row = arow + h;
                Apn[akk * 132 + row] = W1s[(k0n + akk) * 20 + (row & 15)] *
                                       s1s[(k0n + akk) * 9 + (row >> 4)];
            }
        }
        __syncthreads();
    }

#pragma unroll
    for (int rr = 0; rr < 8; ++rr) {
        size_t row = (size_t)r0 + ty * 8 + rr;
        float* qp = g_Q + row * 512 + n0 + 4 * tx;
        float2 f0 = unpack2(acc[rr][0]);
        float2 f1 = unpack2(acc[rr][1]);
        float2 f2 = unpack2(acc[rr][2]);
        float2 f3 = unpack2(acc[rr][3]);
        float4 v0; v0.x = f0.x; v0.y = f0.y; v0.z = f1.x; v0.w = f1.y;
        float4 v1; v1.x = f2.x; v1.y = f2.y; v1.z = f3.x; v1.w = f3.y;
        *reinterpret_cast<float4*>(qp)      = v0;
        *reinterpret_cast<float4*>(qp + 64) = v1;
    }
}

// ---------------- K4b: A = Q D2 Q^T + W1_lo D1 W1_lo^T ; rhs -= Q w ----------------
// rhs2 chains paired into fma2 (bit-exact per lane).
#define K4B_FLOATS (16*520 + 128*68 + 8*512 + 8*64 + 8*64)
#define K4B_SMEM   (K4B_FLOATS * 4)

__global__ __launch_bounds__(256, 2) void k4b_assemble(const float* __restrict__ W1) {
    extern __shared__ __align__(16) float smb[];
    float* W1t = smb;
    float* Qc  = W1t + 16 * 520;
    float* d1s = Qc + 128 * 68;
    float* d2c = d1s + 8 * 512;
    float* wc  = d2c + 8 * 64;

    int tid = threadIdx.x;
    int b0  = blockIdx.x * 8;

    for (int idx = tid; idx < 16 * 512; idx += 256) {
        int i = idx >> 9, k = idx & 511;
        W1t[i * 520 + k] = W1[(16 + i) * 512 + k];
    }
    for (int idx = tid; idx < 8 * 512; idx += 256)
        d1s[idx] = g_g1[(size_t)b0 * 512 + idx];

    int s = tid >> 5, lane = tid & 31;
    int rg = lane >> 3, cg = lane & 7;

    unsigned long long A01[4] = {};
    unsigned long long R01 = 0ull, R23 = 0ull;   // paired rhs2 {0,1},{2,3}

    for (int mc = 0; mc < 8; ++mc) {
        int m0 = mc * 64;
        __syncthreads();
#pragma unroll
        for (int it = 0; it < 8; ++it) {
            int idx = it * 256 + tid;
            int ss = idx >> 8, rem = idx & 255;
            int i = rem >> 4, c4 = rem & 15;
            *reinterpret_cast<float4*>(&Qc[(ss * 16 + i) * 68 + c4 * 4]) =
                *reinterpret_cast<const float4*>(&g_Q[((size_t)(b0 + ss) * 16 + i) * 512 + m0 + c4 * 4]);
        }
        for (int idx = tid; idx < 512; idx += 256) {
            int ss = idx >> 6, m = idx & 63;
            d2c[idx] = g_d2[(size_t)(b0 + ss) * 512 + m0 + m];
            wc[idx]  = g_w [(size_t)(b0 + ss) * 512 + m0 + m];
        }
        __syncthreads();

        const float* qb = Qc + s * 16 * 68;
        const float* dp = d2c + s * 64;
        const float* wp = wc + s * 64;
#pragma unroll 2
        for (int m4 = 0; m4 < 16; ++m4) {
            float d2v[4], wv[4], qj0[4], qj1[4];
            *reinterpret_cast<float4*>(d2v) = *reinterpret_cast<const float4*>(dp + m4 * 4);
            *reinterpret_cast<float4*>(wv)  = *reinterpret_cast<const float4*>(wp + m4 * 4);
            *reinterpret_cast<float4*>(qj0) = *reinterpret_cast<const float4*>(qb + (2 * cg) * 68 + m4 * 4);
            *reinterpret_cast<float4*>(qj1) = *reinterpret_cast<const float4*>(qb + (2 * cg + 1) * 68 + m4 * 4);
            float qi[4][4];
#pragma unroll
            for (int rr = 0; rr < 4; ++rr)
                *reinterpret_cast<float4*>(qi[rr]) =
                    *reinterpret_cast<const float4*>(qb + (4 * rg + rr) * 68 + m4 * 4);
#pragma unroll
            for (int e = 0; e < 4; ++e) {
                unsigned long long qj = pack2f(qj0[e], qj1[e]);
                unsigned long long wv2 = pack2(wv[e]);
#pragma unroll
                for (int rr = 0; rr < 4; ++rr) {
                    float t = qi[rr][e] * d2v[e];
                    fma2(A01[rr], qj, pack2(t));
                }
                fma2(R01, pack2f(qi[0][e], qi[1][e]), wv2);
                fma2(R23, pack2f(qi[2][e], qi[3][e]), wv2);
            }
        }
    }

    // H1 term
    {
        const float* d1p = d1s + s * 512;
#pragma unroll 2
        for (int k4 = 0; k4 < 128; ++k4) {
            float d1v[4], wj0[4], wj1[4];
            *reinterpret_cast<float4*>(d1v) = *reinterpret_cast<const float4*>(d1p + k4 * 4);
            *reinterpret_cast<float4*>(wj0) = *reinterpret_cast<const float4*>(W1t + (2 * cg) * 520 + k4 * 4);
            *reinterpret_cast<float4*>(wj1) = *reinterpret_cast<const float4*>(W1t + (2 * cg + 1) * 520 + k4 * 4);
            float wi[4][4];
#pragma unroll
            for (int rr = 0; rr < 4; ++rr)
                *reinterpret_cast<float4*>(wi[rr]) =
                    *reinterpret_cast<const float4*>(W1t + (4 * rg + rr) * 520 + k4 * 4);
#pragma unroll
            for (int e = 0; e < 4; ++e) {
                unsigned long long wj = pack2f(wj0[e], wj1[e]);
#pragma unroll
                for (int rr = 0; rr < 4; ++rr) {
                    float t = wi[rr][e] * d1v[e];
                    fma2(A01[rr], wj, pack2(t));
                }
            }
        }
    }

    int b = b0 + s;
    float rhs2v[4];
    {
        float2 f = unpack2(R01); rhs2v[0] = f.x; rhs2v[1] = f.y;
        f = unpack2(R23);        rhs2v[2] = f.x; rhs2v[3] = f.y;
    }
#pragma unroll
    for (int rr = 0; rr < 4; ++rr) {
        int i = 4 * rg + rr;
        float* Ar = g_A + ((size_t)b * 16 + i) * 16;
        float2 f = unpack2(A01[rr]);
        Ar[2 * cg]     = f.x;
        Ar[2 * cg + 1] = f.y;
        if (cg == 0) {
            size_t ob = (size_t)b * 16 + i;
            g_rhs[ob] -= rhs2v[rr];
        }
    }
}

// ---------------- K5 (round-15) ----------------
#define PINV_RCOND 1.9073486e-5f
#define JACOBI_SWEEPS 6

__global__ __launch_bounds__(256) void k5_pinv(const float* __restrict__ x,
                                               float* __restrict__ out) {
    __shared__ float sm[16 * 592];
    int tid = threadIdx.x;
    int sI = tid >> 4;
    int r  = tid & 15;
    int b  = blockIdx.x * 16 + sI;

    float* As = sm + sI * 592;
    float* Vs = As + 272;
    float* ys = Vs + 272;
    float* rs = ys + 16;

    {
        const float* Ag = g_A + ((size_t)b * 16 + r) * 16;
#pragma unroll
        for (int j = 0; j < 16; ++j) {
            As[r * 17 + j] = Ag[j];
            Vs[r * 17 + j] = (r == j) ? 1.f : 0.f;
        }
        rs[r] = g_rhs[(size_t)b * 16 + r];
    }
    __syncwarp();

    for (int sweep = 0; sweep < JACOBI_SWEEPS; ++sweep) {
        for (int p = 0; p < 15; ++p) {
            for (int q = p + 1; q < 16; ++q) {
                float apq = As[p * 17 + q];
                float app = As[p * 17 + p];
                float aqq = As[q * 17 + q];
                float aip = As[r * 17 + p];
                float aiq = As[r * 17 + q];
                float vip = Vs[r * 17 + p];
                float viq = Vs[r * 17 + q];
                __syncwarp();
                float tau = (aqq - app) / (2.f * apq);
                float tt  = copysignf(1.f, tau) / (fabsf(tau) + sqrtf(fmaf(tau, tau, 1.f)));
                float t   = (fabsf(apq) > 0.f) ? tt : 0.f;
                float c   = 1.f / sqrtf(fmaf(t, t, 1.f));
                float s   = t * c;
                float nip = c * aip - s * aiq;
                float niq = s * aip + c * aiq;
                if (r != p && r != q) {
                    As[r * 17 + p] = nip; As[p * 17 + r] = nip;
                    As[r * 17 + q] = niq; As[q * 17 + r] = niq;
                }
                if (r == p) {
                    As[p * 17 + p] = app - t * apq;
                    As[q * 17 + q] = aqq + t * apq;
                    As[p * 17 + q] = 0.f;
                    As[q * 17 + p] = 0.f;
                }
                Vs[r * 17 + p] = c * vip - s * viq;
                Vs[r * 17 + q] = s * vip + c * viq;
                __syncwarp();
            }
        }
    }

    float lam = As[r * 17 + r];
    float m = fabsf(lam);
#pragma unroll
    for (int off = 8; off > 0; off >>= 1)
        m = fmaxf(m, __shfl_xor_sync(0xffffffffu, m, off));
    float cutoff = PINV_RCOND * m;

    float acc = 0.f;
#pragma unroll
    for (int j = 0; j < 16; ++j) acc = fmaf(Vs[j * 17 + r], rs[j], acc);
    ys[r] = (fabsf(lam) > cutoff) ? (acc / lam) : 0.f;
    __syncwarp();

    float qdd = 0.f;
#pragma unroll
    for (int j = 0; j < 16; ++j) qdd = fmaf(Vs[r * 17 + j], ys[j], qdd);

    out[(size_t)b * 32 + 16 + r] = qdd;
    out[(size_t)b * 32 + r]      = x[(size_t)b * 32 + 16 + r];
}

// ---------------- launch (k4a 4th for ncu capture) ----------------
extern "C" void kernel_launch(void* const* d_in, const int* in_sizes, int n_in,
                              void* d_out, int out_size) {
    const float* x  = (const float*)d_in[0];
    const float* W1 = (const float*)d_in[1];
    const float* b1 = (const float*)d_in[2];
    const float* W2 = (const float*)d_in[3];
    const float* b2 = (const float*)d_in[4];
    const float* W3 = (const float*)d_in[5];
    float* out = (float*)d_out;
    (void)in_sizes; (void)n_in; (void)out_size;

    cudaFuncSetAttribute(k1_layer1,    cudaFuncAttributeMaxDynamicSharedMemorySize, K1_SMEM);
    cudaFuncSetAttribute(k_jac,        cudaFuncAttributeMaxDynamicSharedMemorySize, KJ_SMEM);
    cudaFuncSetAttribute(k4a_qgemm,    cudaFuncAttributeMaxDynamicSharedMemorySize, K4A_SMEM);
    cudaFuncSetAttribute(k4b_assemble, cudaFuncAttributeMaxDynamicSharedMemorySize, K4B_SMEM);

    k1_layer1<<<BS / 8, 256, K1_SMEM>>>(x, W1, b1);
    k2_layer2<<<dim3(BS / 64, HID / 128), 256>>>(W2, b2, W3);
    k3_g1<<<dim3(BS / 64, HID / 128), 256>>>(W2);
    k4a_qgemm<<<dim3(BS * 16 / 128, HID / 128), 256, K4A_SMEM>>>(W1, W2);   // 4th: gets profiled
    k_jac<<<BS / 8, 256, KJ_SMEM>>>(W1);
    k4b_assemble<<<BS / 8, 256, K4B_SMEM>>>(W1);
    k5_pinv<<<BS / 16, 256>>>(x, out);
}